// round 15
// baseline (speedup 1.0000x reference)
#include <cuda_runtime.h>
#include <cuda_fp16.h>

// EdgeMLP via 2-term split-fp16 warp-level MMA (mma.sync m16n8k16).
// out = silu( silu( LN( [src|edge] @ W1 + b1 ) ) @ W2 + b2 ), fp32 I/O.
// x ~ fp16(x);  w = wh + wl (fp16 each);  x*w ~= xh*wh + xh*wl.
// v6: lo-term MMAs use f16 accumulators (2x HMMA rate; rounding ~2^-22 rel),
// merged into the f32 hi-term accumulators once per GEMM phase.
// Keeps v5's tanh-SiLU and split src prefetch.

typedef unsigned int u32;
typedef unsigned short u16;
typedef unsigned long long u64;

static constexpr int THREADS = 512;
static constexpr int BR = 128, NODE = 128, EDGED = 64, OUTD = 128;

// ---- smem byte offsets ----
static constexpr int OFF_W1AH = 0;        // W1 k<128:  [n=128][k=128] fp16 hi
static constexpr int OFF_W1AL = 32768;    //            fp16 lo
static constexpr int OFF_W1BH = 65536;    // W1 k>=128: [128][64]
static constexpr int OFF_W1BL = 81920;
static constexpr int OFF_W2H  = 98304;    // [128][128]
static constexpr int OFF_W2L  = 131072;
static constexpr int OFF_BUF  = 163840;   // 64KB: X/H fp16 (first 32KB) +
                                          // edge raw/fp16 (second 32KB).
                                          // Raw next-src split: rows 0-63 in
                                          // second half, rows 64-127 in first.
static constexpr int OFF_B1 = 229376, OFF_B2 = 229888;
static constexpr int OFF_G  = 230400, OFF_BT = 230912;
static constexpr int SMEM_BYTES = 231424; // <= 232448

__device__ __forceinline__ u32 smem_u32(const void* p) {
    u32 a;
    asm("{ .reg .u64 t; cvta.to.shared.u64 t, %1; cvt.u32.u64 %0, t; }"
        : "=r"(a) : "l"(p));
    return a;
}
// silu(y) = t + t*tanh(t), t = y/2  (single MUFU op)
__device__ __forceinline__ float silu_f(float y) {
    const float t = 0.5f * y;
    float s;
    asm("tanh.approx.f32 %0, %1;" : "=f"(s) : "f"(t));
    return fmaf(t, s, t);
}
// fp16(a) in low half, fp16(b) in high half
__device__ __forceinline__ u32 pack_f16x2(float a, float b) {
    u32 r;
    asm("cvt.rn.f16x2.f32 %0, %1, %2;" : "=r"(r) : "f"(b), "f"(a));
    return r;
}
__device__ __forceinline__ void cp16(u32 dst, const void* gsrc) {
    asm volatile("cp.async.ca.shared.global [%0], [%1], 16;"
                 :: "r"(dst), "l"(gsrc) : "memory");
}
#define CP_COMMIT() asm volatile("cp.async.commit_group;" ::: "memory")
#define CP_WAIT0()  asm volatile("cp.async.wait_group 0;" ::: "memory")

// 16B chunk address of (row, k) in a [rows][NC*8 k] fp16 tile, chunk-swizzled.
template <int NC>
__device__ __forceinline__ u32 fr_addr(u32 base, int row, int k) {
    return base + (((row * NC) + ((k >> 3) ^ (row & 7))) << 4);
}

#define LDSM4(R0, R1, R2, R3, A)                                          \
    asm volatile("ldmatrix.sync.aligned.m8n8.x4.shared.b16 {%0,%1,%2,%3}, [%4];" \
                 : "=r"(R0), "=r"(R1), "=r"(R2), "=r"(R3) : "r"(A))

__device__ __forceinline__ void mma_f32acc(float* c, u32 a0, u32 a1, u32 a2, u32 a3,
                                           u32 b0, u32 b1) {
    asm volatile(
        "mma.sync.aligned.m16n8k16.row.col.f32.f16.f16.f32 "
        "{%0,%1,%2,%3}, {%4,%5,%6,%7}, {%8,%9}, {%0,%1,%2,%3};"
        : "+f"(c[0]), "+f"(c[1]), "+f"(c[2]), "+f"(c[3])
        : "r"(a0), "r"(a1), "r"(a2), "r"(a3), "r"(b0), "r"(b1));
}
// f16 accumulators: D = {c0,c1|c2,c3} packed f16x2 in 2 regs; 2x rate.
__device__ __forceinline__ void mma_f16acc(u32* c, u32 a0, u32 a1, u32 a2, u32 a3,
                                           u32 b0, u32 b1) {
    asm volatile(
        "mma.sync.aligned.m16n8k16.row.col.f16.f16.f16.f16 "
        "{%0,%1}, {%2,%3,%4,%5}, {%6,%7}, {%0,%1};"
        : "+r"(c[0]), "+r"(c[1])
        : "r"(a0), "r"(a1), "r"(a2), "r"(a3), "r"(b0), "r"(b1));
}

// One k16 step: accF += A x Bh (f32 acc), accH += A x Bl (f16 acc, 2x rate).
template <int NCA, int NCB>
__device__ __forceinline__ void k_step(u32 aP, u32 bH, u32 bL,
                                       int wm, int wn, int k0,
                                       float accF[2][4][4], u32 accH[2][4][2],
                                       int lane) {
    const int la7 = lane & 7;
    const int arow = wm * 32 + la7 + (((lane >> 3) & 1) << 3);
    const int ak   = k0 + ((lane >> 4) << 3);
    const int brow = wn * 32 + la7 + ((lane >> 4) << 3);
    const int bk   = k0 + (((lane >> 3) & 1) << 3);

    u32 ah[8], bh[8], bl[8];
    LDSM4(ah[0], ah[1], ah[2], ah[3], fr_addr<NCA>(aP, arow, ak));
    LDSM4(ah[4], ah[5], ah[6], ah[7], fr_addr<NCA>(aP, arow + 16, ak));
    LDSM4(bh[0], bh[1], bh[2], bh[3], fr_addr<NCB>(bH, brow, bk));
    LDSM4(bh[4], bh[5], bh[6], bh[7], fr_addr<NCB>(bH, brow + 16, bk));
    LDSM4(bl[0], bl[1], bl[2], bl[3], fr_addr<NCB>(bL, brow, bk));
    LDSM4(bl[4], bl[5], bl[6], bl[7], fr_addr<NCB>(bL, brow + 16, bk));

#pragma unroll
    for (int mt = 0; mt < 2; mt++) {
        const u32* A = ah + 4 * mt;
#pragma unroll
        for (int nt = 0; nt < 4; nt++) {
            mma_f32acc(accF[mt][nt], A[0], A[1], A[2], A[3],
                       bh[2 * nt], bh[2 * nt + 1]);
            mma_f16acc(accH[mt][nt], A[0], A[1], A[2], A[3],
                       bl[2 * nt], bl[2 * nt + 1]);
        }
    }
}

__device__ __forceinline__ void merge_lo(float accF[2][4][4], u32 accH[2][4][2]) {
#pragma unroll
    for (int mt = 0; mt < 2; mt++)
#pragma unroll
        for (int nt = 0; nt < 4; nt++) {
            const float2 p0 = __half22float2(*(const __half2*)&accH[mt][nt][0]);
            const float2 p1 = __half22float2(*(const __half2*)&accH[mt][nt][1]);
            accF[mt][nt][0] += p0.x;
            accF[mt][nt][1] += p0.y;
            accF[mt][nt][2] += p1.x;
            accF[mt][nt][3] += p1.y;
        }
}

__global__ void __launch_bounds__(THREADS, 1)
edge_mlp_mma(const float* __restrict__ src, const float* __restrict__ edg,
             const float* __restrict__ W1,  const float* __restrict__ b1,
             const float* __restrict__ gam, const float* __restrict__ bet,
             const float* __restrict__ W2,  const float* __restrict__ b2,
             float* __restrict__ out, int E, int ntiles) {
    extern __shared__ char smc[];
    const u32 sb = smem_u32(smc);
    const int tid = threadIdx.x;
    const int warp = tid >> 5, lane = tid & 31;
    const int wm = warp >> 2, wn = warp & 3;   // warp: rows wm*32, cols wn*32
    const int g = lane >> 2, tig = lane & 3;
    const u32 bufX = sb + OFF_BUF;             // X/H fp16 [128][128] (32KB)
    const u32 bufE = sb + OFF_BUF + 32768;     // edge raw/fp16; src raw rows 0-63

    // raw-src split layout: chunk i (row = i>>5): rows 0-63 -> bufE + i*16,
    // rows 64-127 -> bufX + (i-2048)*16.
    auto pf_lo = [&](int rowbase) {
        const float4* s4 = (const float4*)(src + (size_t)rowbase * NODE);
#pragma unroll
        for (int j = 0; j < 4; j++) {
            const int i = tid + j * THREADS;        // [0,2048)
            const int r = i >> 5;
            if (rowbase + r < E) cp16(bufE + (i << 4), s4 + i);
            else *(float4*)(smc + OFF_BUF + 32768 + (i << 4)) =
                     make_float4(0.f, 0.f, 0.f, 0.f);
        }
    };
    auto pf_hi = [&](int rowbase) {
        const float4* s4 = (const float4*)(src + (size_t)rowbase * NODE);
#pragma unroll
        for (int j = 0; j < 4; j++) {
            const int i = 2048 + tid + j * THREADS; // [2048,4096)
            const int r = i >> 5;
            if (rowbase + r < E) cp16(bufX + ((i - 2048) << 4), s4 + i);
            else *(float4*)(smc + OFF_BUF + ((i - 2048) << 4)) =
                     make_float4(0.f, 0.f, 0.f, 0.f);
        }
    };

    // ---- prefetch first tile's raw src ----
    {
        const int rowbase = blockIdx.x * BR;
        pf_lo(rowbase);
        pf_hi(rowbase);
        CP_COMMIT();
    }

    // ---- one-time: split weights into fp16 hi/lo [n][k] swizzled tiles ----
    for (int i = tid; i < 192 * 128; i += THREADS) {
        const int k = i >> 7, n = i & 127;
        const float w = W1[i];
        const __half hh = __float2half_rn(w);
        const __half hl = __float2half_rn(w - __half2float(hh));
        if (k < 128) {
            const u32 byte = ((n * 16 + ((k >> 3) ^ (n & 7))) << 4) + ((k & 7) << 1);
            *(u16*)(smc + OFF_W1AH + byte) = __half_as_ushort(hh);
            *(u16*)(smc + OFF_W1AL + byte) = __half_as_ushort(hl);
        } else {
            const int k2 = k - 128;
            const u32 byte = ((n * 8 + ((k2 >> 3) ^ (n & 7))) << 4) + ((k2 & 7) << 1);
            *(u16*)(smc + OFF_W1BH + byte) = __half_as_ushort(hh);
            *(u16*)(smc + OFF_W1BL + byte) = __half_as_ushort(hl);
        }
    }
    for (int i = tid; i < 128 * 128; i += THREADS) {
        const int k = i >> 7, n = i & 127;
        const float w = W2[i];
        const __half hh = __float2half_rn(w);
        const __half hl = __float2half_rn(w - __half2float(hh));
        const u32 byte = ((n * 16 + ((k >> 3) ^ (n & 7))) << 4) + ((k & 7) << 1);
        *(u16*)(smc + OFF_W2H + byte) = __half_as_ushort(hh);
        *(u16*)(smc + OFF_W2L + byte) = __half_as_ushort(hl);
    }
    if (tid < 128) {
        ((float*)(smc + OFF_B1))[tid] = b1[tid];
        ((float*)(smc + OFF_B2))[tid] = b2[tid];
        ((float*)(smc + OFF_G))[tid]  = gam[tid];
        ((float*)(smc + OFF_BT))[tid] = bet[tid];
    }
    const float* b1f = (const float*)(smc + OFF_B1);
    const float* b2f = (const float*)(smc + OFF_B2);
    const float* gf  = (const float*)(smc + OFF_G);
    const float* btf = (const float*)(smc + OFF_BT);

    for (int tile = blockIdx.x; tile < ntiles; tile += gridDim.x) {
        const int rowbase = tile * BR;
        const bool full = (rowbase + BR <= E);
        const int ntile = tile + gridDim.x;

        // ---- convert raw src (split layout) -> X fp16 (first 32KB) ----
        CP_WAIT0();
        __syncthreads();   // cp data landed everywhere; weights ready (iter 0)
        {
            float4 xa[8];
#pragma unroll
            for (int j = 0; j < 8; j++) {
                const int i = tid + j * THREADS;
                const int off = (i < 2048) ? (32768 + (i << 4)) : ((i - 2048) << 4);
                xa[j] = *(const float4*)(smc + OFF_BUF + off);
            }
            __syncthreads();   // all raw reads done before overwriting
#pragma unroll
            for (int j = 0; j < 8; j++) {
                const int i = tid + j * THREADS;
                const int r = i >> 5, c4 = i & 31;
                const float4 v = xa[j];
                const u32 byte = ((r * 16 + ((c4 >> 1) ^ (r & 7))) << 4) + ((c4 & 1) << 3);
                *(u64*)(smc + OFF_BUF + byte) =
                    (u64)pack_f16x2(v.x, v.y) | ((u64)pack_f16x2(v.z, v.w) << 32);
            }
            // prefetch edge raw (32KB) into bufE — overlaps GEMM1-A
            const float4* e4 = (const float4*)(edg + (size_t)rowbase * EDGED);
#pragma unroll
            for (int j = 0; j < 4; j++) {
                const int i = tid + j * THREADS;
                const int r = i >> 4;
                if (full || rowbase + r < E) cp16(bufE + (i << 4), e4 + i);
                else *(float4*)(smc + OFF_BUF + 32768 + (i << 4)) =
                         make_float4(0.f, 0.f, 0.f, 0.f);
            }
            CP_COMMIT();
        }
        __syncthreads();

        // ---- GEMM1 part A: src x W1[k<128] ----
        float accF[2][4][4];
        u32 accH[2][4][2];
#pragma unroll
        for (int mt = 0; mt < 2; mt++)
#pragma unroll
            for (int nt = 0; nt < 4; nt++) {
#pragma unroll
                for (int q = 0; q < 4; q++) accF[mt][nt][q] = 0.f;
                accH[mt][nt][0] = 0u;
                accH[mt][nt][1] = 0u;
            }
#pragma unroll 2
        for (int ks = 0; ks < 8; ks++)
            k_step<16, 16>(bufX, sb + OFF_W1AH, sb + OFF_W1AL,
                           wm, wn, ks * 16, accF, accH, lane);

        // ---- convert edge raw -> fp16 in place (bufE) ----
        CP_WAIT0();
        {
            float4 ea[4];
#pragma unroll
            for (int j = 0; j < 4; j++)
                ea[j] = *(const float4*)(smc + OFF_BUF + 32768 + ((tid + j * THREADS) << 4));
            __syncthreads();   // edge raw reads done (also closes GEMM1-A reads)
#pragma unroll
            for (int j = 0; j < 4; j++) {
                const int i = tid + j * THREADS;
                const int r = i >> 4, c4 = i & 15;
                const float4 v = ea[j];
                const u32 byte = ((r * 8 + ((c4 >> 1) ^ (r & 7))) << 4) + ((c4 & 1) << 3);
                *(u64*)(smc + OFF_BUF + 32768 + byte) =
                    (u64)pack_f16x2(v.x, v.y) | ((u64)pack_f16x2(v.z, v.w) << 32);
            }
        }
        __syncthreads();

        // ---- GEMM1 part B: edge x W1[k>=128] ----
#pragma unroll 2
        for (int ks = 0; ks < 4; ks++)
            k_step<8, 8>(bufE, sb + OFF_W1BH, sb + OFF_W1BL,
                         wm, wn, ks * 16, accF, accH, lane);
        merge_lo(accF, accH);
        __syncthreads();   // edge reads done; bufE free

        // ---- prefetch next tile's src rows 0-63 into bufE (long slack) ----
        if (ntile < ntiles) pf_lo(ntile * BR);
        CP_COMMIT();

        // ---- bias + LN partial sums (thread covers 4 rows x 8 cols) ----
        float s1[4] = {0.f, 0.f, 0.f, 0.f}, s2[4] = {0.f, 0.f, 0.f, 0.f};
#pragma unroll
        for (int mt = 0; mt < 2; mt++)
#pragma unroll
            for (int nt = 0; nt < 4; nt++) {
                const int c0 = wn * 32 + nt * 8 + 2 * tig;
                float* C = accF[mt][nt];
                C[0] += b1f[c0]; C[1] += b1f[c0 + 1];
                C[2] += b1f[c0]; C[3] += b1f[c0 + 1];
                s1[2 * mt]     += C[0] + C[1];
                s2[2 * mt]     += C[0] * C[0] + C[1] * C[1];
                s1[2 * mt + 1] += C[2] + C[3];
                s2[2 * mt + 1] += C[2] * C[2] + C[3] * C[3];
            }
#pragma unroll
        for (int j = 0; j < 4; j++) {
            s1[j] += __shfl_xor_sync(0xffffffffu, s1[j], 1);
            s1[j] += __shfl_xor_sync(0xffffffffu, s1[j], 2);
            s2[j] += __shfl_xor_sync(0xffffffffu, s2[j], 1);
            s2[j] += __shfl_xor_sync(0xffffffffu, s2[j], 2);
        }
        float2* part = (float2*)(smc + OFF_BUF);   // first 4KB of X region
        if (tig == 0) {
#pragma unroll
            for (int j = 0; j < 4; j++) {
                const int row = wm * 32 + ((j >> 1) << 4) + ((j & 1) << 3) + g;
                part[row * 4 + wn] = make_float2(s1[j], s2[j]);
            }
        }
        __syncthreads();

        float mus[4], rss[4];
#pragma unroll
        for (int j = 0; j < 4; j++) {
            const int row = wm * 32 + ((j >> 1) << 4) + ((j & 1) << 3) + g;
            const float2 q0 = part[row * 4 + 0], q1 = part[row * 4 + 1];
            const float2 q2 = part[row * 4 + 2], q3 = part[row * 4 + 3];
            const float m1 = (q0.x + q1.x + q2.x + q3.x) * (1.0f / 128.0f);
            const float m2 = (q0.y + q1.y + q2.y + q3.y) * (1.0f / 128.0f);
            mus[j] = m1;
            rss[j] = rsqrtf(m2 - m1 * m1 + 1e-5f);
        }
        __syncthreads();   // partials consumed; X region writable as H

        // ---- LN apply + SiLU -> H fp16 (swizzled, first 32KB) ----
#pragma unroll
        for (int mt = 0; mt < 2; mt++)
#pragma unroll
            for (int nt = 0; nt < 4; nt++) {
                const int c0 = wn * 32 + nt * 8 + 2 * tig;
                float* C = accF[mt][nt];
#pragma unroll
                for (int h = 0; h < 2; h++) {
                    const int j = 2 * mt + h;
                    const int row = wm * 32 + mt * 16 + h * 8 + g;
                    const float y0 = silu_f((C[2 * h + 0] - mus[j]) * rss[j] * gf[c0]     + btf[c0]);
                    const float y1 = silu_f((C[2 * h + 1] - mus[j]) * rss[j] * gf[c0 + 1] + btf[c0 + 1]);
                    const u32 byte = ((row * 16 + ((c0 >> 3) ^ (row & 7))) << 4)
                                   + ((c0 & 7) << 1);
                    *(u32*)(smc + OFF_BUF + byte) = pack_f16x2(y0, y1);
                }
            }
        __syncthreads();

        // ---- GEMM2: H x W2 ----
#pragma unroll
        for (int mt = 0; mt < 2; mt++)
#pragma unroll
            for (int nt = 0; nt < 4; nt++) {
#pragma unroll
                for (int q = 0; q < 4; q++) accF[mt][nt][q] = 0.f;
                accH[mt][nt][0] = 0u;
                accH[mt][nt][1] = 0u;
            }
#pragma unroll 2
        for (int ks = 0; ks < 8; ks++)
            k_step<16, 16>(bufX, sb + OFF_W2H, sb + OFF_W2L,
                           wm, wn, ks * 16, accF, accH, lane);
        merge_lo(accF, accH);
        __syncthreads();   // all warps done reading H; bufX free

        // ---- prefetch next tile's src rows 64-127 into bufX ----
        if (ntile < ntiles) pf_hi(ntile * BR);
        CP_COMMIT();

        // ---- epilogue: bias + SiLU + store ----
#pragma unroll
        for (int mt = 0; mt < 2; mt++)
#pragma unroll
            for (int nt = 0; nt < 4; nt++) {
                const int c0 = wn * 32 + nt * 8 + 2 * tig;
                float* C = accF[mt][nt];
#pragma unroll
                for (int h = 0; h < 2; h++) {
                    const int row = rowbase + wm * 32 + mt * 16 + h * 8 + g;
                    if (row < E) {
                        float2 o;
                        o.x = silu_f(C[2 * h + 0] + b2f[c0]);
                        o.y = silu_f(C[2 * h + 1] + b2f[c0 + 1]);
                        *(float2*)(out + (size_t)row * OUTD + c0) = o;
                    }
                }
            }
    }
}

extern "C" void kernel_launch(void* const* d_in, const int* in_sizes, int n_in,
                              void* d_out, int out_size) {
    const float* src = (const float*)d_in[0];
    const float* edg = (const float*)d_in[1];
    const float* W1  = (const float*)d_in[2];
    const float* b1  = (const float*)d_in[3];
    const float* gam = (const float*)d_in[4];
    const float* bet = (const float*)d_in[5];
    const float* W2  = (const float*)d_in[6];
    const float* b2  = (const float*)d_in[7];
    float* out = (float*)d_out;

    const int E = in_sizes[0] / NODE;
    const int ntiles = (E + BR - 1) / BR;

    cudaFuncSetAttribute(edge_mlp_mma,
                         cudaFuncAttributeMaxDynamicSharedMemorySize, SMEM_BYTES);

    int nsm = 148;
    if (cudaDeviceGetAttribute(&nsm, cudaDevAttrMultiProcessorCount, 0) != cudaSuccess
        || nsm <= 0)
        nsm = 148;
    const int grid = nsm < ntiles ? nsm : ntiles;

    edge_mlp_mma<<<grid, THREADS, SMEM_BYTES>>>(src, edg, W1, b1, gam, bet,
                                                W2, b2, out, E, ntiles);
}

// round 16
// speedup vs baseline: 1.2381x; 1.2381x over previous
#include <cuda_runtime.h>
#include <cuda_fp16.h>

// EdgeMLP via 2-term split-fp16 warp-level MMA (mma.sync m16n8k16, f32 acc).
// out = silu( silu( LN( [src|edge] @ W1 + b1 ) ) @ W2 + b2 ), fp32 I/O.
// x ~ fp16(x);  w = wh + wl (fp16 each);  x*w ~= xh*wh + xh*wl.
//
// v7: the CTA is 4 independent 128-thread pipelines (one per 32-row group).
// Every intra-tile dependency is closed within a group (staging, LN, H,
// GEMM A-side, epilogue), so all syncs are bar.sync <id>,128 — groups drift
// into anti-phase and one group's LSU/ALU phases overlap another's MMAs.
// Per-group 16KB BUF slice: [X/H fp16 8K][edge fp16 4K][spare 4K]; next-tile
// raw src (16K) parks across the whole slice after own GEMM2.

typedef unsigned int u32;
typedef unsigned short u16;
typedef unsigned long long u64;

static constexpr int THREADS = 512;
static constexpr int BR = 128, NODE = 128, EDGED = 64, OUTD = 128;

// ---- smem byte offsets ----
static constexpr int OFF_W1AH = 0;        // W1 k<128:  [n=128][k=128] fp16 hi
static constexpr int OFF_W1AL = 32768;
static constexpr int OFF_W1BH = 65536;    // W1 k>=128: [128][64]
static constexpr int OFF_W1BL = 81920;
static constexpr int OFF_W2H  = 98304;    // [128][128]
static constexpr int OFF_W2L  = 131072;
static constexpr int OFF_BUF  = 163840;   // 4 x 16KB group slices
static constexpr int OFF_B1 = 229376, OFF_B2 = 229888;
static constexpr int OFF_G  = 230400, OFF_BT = 230912;
static constexpr int SMEM_BYTES = 231424; // <= 232448

__device__ __forceinline__ u32 smem_u32(const void* p) {
    u32 a;
    asm("{ .reg .u64 t; cvta.to.shared.u64 t, %1; cvt.u32.u64 %0, t; }"
        : "=r"(a) : "l"(p));
    return a;
}
// silu(y) = t + t*tanh(t), t = y/2  (single MUFU op)
__device__ __forceinline__ float silu_f(float y) {
    const float t = 0.5f * y;
    float s;
    asm("tanh.approx.f32 %0, %1;" : "=f"(s) : "f"(t));
    return fmaf(t, s, t);
}
__device__ __forceinline__ u32 pack_f16x2(float a, float b) {
    u32 r;
    asm("cvt.rn.f16x2.f32 %0, %1, %2;" : "=r"(r) : "f"(b), "f"(a));
    return r;
}
__device__ __forceinline__ void cp16(u32 dst, const void* gsrc) {
    asm volatile("cp.async.ca.shared.global [%0], [%1], 16;"
                 :: "r"(dst), "l"(gsrc) : "memory");
}
#define CP_COMMIT() asm volatile("cp.async.commit_group;" ::: "memory")
#define CP_WAIT0()  asm volatile("cp.async.wait_group 0;" ::: "memory")

// 16B chunk address of (row, k) in a [rows][NC*8 k] fp16 tile, chunk-swizzled.
template <int NC>
__device__ __forceinline__ u32 fr_addr(u32 base, int row, int k) {
    return base + (((row * NC) + ((k >> 3) ^ (row & 7))) << 4);
}

#define LDSM4(R0, R1, R2, R3, A)                                          \
    asm volatile("ldmatrix.sync.aligned.m8n8.x4.shared.b16 {%0,%1,%2,%3}, [%4];" \
                 : "=r"(R0), "=r"(R1), "=r"(R2), "=r"(R3) : "r"(A))

__device__ __forceinline__ void mma_f16(float* c, u32 a0, u32 a1, u32 a2, u32 a3,
                                        u32 b0, u32 b1) {
    asm volatile(
        "mma.sync.aligned.m16n8k16.row.col.f32.f16.f16.f32 "
        "{%0,%1,%2,%3}, {%4,%5,%6,%7}, {%8,%9}, {%0,%1,%2,%3};"
        : "+f"(c[0]), "+f"(c[1]), "+f"(c[2]), "+f"(c[3])
        : "r"(a0), "r"(a1), "r"(a2), "r"(a3), "r"(b0), "r"(b1));
}

// One k16 step; A rows are GROUP-LOCAL (0..31 via mt).
template <int NCA, int NCB>
__device__ __forceinline__ void k_step(u32 aP, u32 bH, u32 bL,
                                       int wn, int k0,
                                       float acc[2][4][4], int lane) {
    const int la7 = lane & 7;
    const int arow = la7 + (((lane >> 3) & 1) << 3);          // local 0..15
    const int ak   = k0 + ((lane >> 4) << 3);
    const int brow = wn * 32 + la7 + ((lane >> 4) << 3);
    const int bk   = k0 + (((lane >> 3) & 1) << 3);

    u32 ah[8], bh[8], bl[8];
    LDSM4(ah[0], ah[1], ah[2], ah[3], fr_addr<NCA>(aP, arow, ak));
    LDSM4(ah[4], ah[5], ah[6], ah[7], fr_addr<NCA>(aP, arow + 16, ak));
    LDSM4(bh[0], bh[1], bh[2], bh[3], fr_addr<NCB>(bH, brow, bk));
    LDSM4(bh[4], bh[5], bh[6], bh[7], fr_addr<NCB>(bH, brow + 16, bk));
    LDSM4(bl[0], bl[1], bl[2], bl[3], fr_addr<NCB>(bL, brow, bk));
    LDSM4(bl[4], bl[5], bl[6], bl[7], fr_addr<NCB>(bL, brow + 16, bk));

#pragma unroll
    for (int mt = 0; mt < 2; mt++) {
        const u32* A = ah + 4 * mt;
#pragma unroll
        for (int nt = 0; nt < 4; nt++) {
            float* C = acc[mt][nt];
            mma_f16(C, A[0], A[1], A[2], A[3], bh[2 * nt], bh[2 * nt + 1]);
            mma_f16(C, A[0], A[1], A[2], A[3], bl[2 * nt], bl[2 * nt + 1]);
        }
    }
}

__global__ void __launch_bounds__(THREADS, 1)
edge_mlp_mma(const float* __restrict__ src, const float* __restrict__ edg,
             const float* __restrict__ W1,  const float* __restrict__ b1,
             const float* __restrict__ gam, const float* __restrict__ bet,
             const float* __restrict__ W2,  const float* __restrict__ b2,
             float* __restrict__ out, int E, int ntiles) {
    extern __shared__ char smc[];
    const u32 sb = smem_u32(smc);
    const int tid = threadIdx.x;
    const int warp = tid >> 5, lane = tid & 31;
    const int wm = warp >> 2, wn = warp & 3;   // group wm; warp cols wn*32
    const int gt = tid & 127;                  // thread id within group
    const int g = lane >> 2, tig = lane & 3;
    const int barid = wm + 1;                  // named barrier per group

    // group slice: [X/H 8K][E 4K][spare 4K]
    const u32 Bw  = sb + OFF_BUF + wm * 16384;
    char* Bc      = smc + OFF_BUF + wm * 16384;
    const u32 bufX = Bw;                 // X/H fp16 [32][16 chunks]
    const u32 bufE = Bw + 8192;          // edge fp16 [32][8 chunks]

#define GBAR() asm volatile("bar.sync %0, 128;" :: "r"(barid) : "memory")

    // ---- group-scoped prefetch of own 32 raw src rows (16KB) ----
    auto pf_src = [&](int tilerow) {
        const int r0g = tilerow + wm * 32;
#pragma unroll
        for (int jj = 0; jj < 8; jj++) {
            const int j = gt + jj * 128;          // 0..1023
            const int r = j >> 5, c4 = j & 31;
            if (r0g + r < E)
                cp16(Bw + (j << 4), src + (size_t)(r0g + r) * NODE + c4 * 4);
            else
                *(float4*)(Bc + (j << 4)) = make_float4(0.f, 0.f, 0.f, 0.f);
        }
        CP_COMMIT();
    };

    // ---- first tile's raw src ----
    if (blockIdx.x < ntiles) pf_src(blockIdx.x * BR);
    else CP_COMMIT();

    // ---- one-time: split weights into fp16 hi/lo [n][k] swizzled tiles ----
    for (int i = tid; i < 192 * 128; i += THREADS) {
        const int k = i >> 7, n = i & 127;
        const float w = W1[i];
        const __half hh = __float2half_rn(w);
        const __half hl = __float2half_rn(w - __half2float(hh));
        if (k < 128) {
            const u32 byte = ((n * 16 + ((k >> 3) ^ (n & 7))) << 4) + ((k & 7) << 1);
            *(u16*)(smc + OFF_W1AH + byte) = __half_as_ushort(hh);
            *(u16*)(smc + OFF_W1AL + byte) = __half_as_ushort(hl);
        } else {
            const int k2 = k - 128;
            const u32 byte = ((n * 8 + ((k2 >> 3) ^ (n & 7))) << 4) + ((k2 & 7) << 1);
            *(u16*)(smc + OFF_W1BH + byte) = __half_as_ushort(hh);
            *(u16*)(smc + OFF_W1BL + byte) = __half_as_ushort(hl);
        }
    }
    for (int i = tid; i < 128 * 128; i += THREADS) {
        const int k = i >> 7, n = i & 127;
        const float w = W2[i];
        const __half hh = __float2half_rn(w);
        const __half hl = __float2half_rn(w - __half2float(hh));
        const u32 byte = ((n * 16 + ((k >> 3) ^ (n & 7))) << 4) + ((k & 7) << 1);
        *(u16*)(smc + OFF_W2H + byte) = __half_as_ushort(hh);
        *(u16*)(smc + OFF_W2L + byte) = __half_as_ushort(hl);
    }
    if (tid < 128) {
        ((float*)(smc + OFF_B1))[tid] = b1[tid];
        ((float*)(smc + OFF_B2))[tid] = b2[tid];
        ((float*)(smc + OFF_G))[tid]  = gam[tid];
        ((float*)(smc + OFF_BT))[tid] = bet[tid];
    }
    const float* b1f = (const float*)(smc + OFF_B1);
    const float* b2f = (const float*)(smc + OFF_B2);
    const float* gf  = (const float*)(smc + OFF_G);
    const float* btf = (const float*)(smc + OFF_BT);

    __syncthreads();   // weights visible; ONLY CTA-wide sync in the kernel

    for (int tile = blockIdx.x; tile < ntiles; tile += gridDim.x) {
        const int rowbase = tile * BR;
        const int r0g = rowbase + wm * 32;       // group's global row base
        const int ntile = tile + gridDim.x;

        // ---- raw src -> X fp16 (park in regs, group barrier, store) ----
        CP_WAIT0();                              // own cp.asyncs (own chunks)
        {
            float4 xa[8];
#pragma unroll
            for (int jj = 0; jj < 8; jj++)
                xa[jj] = *(const float4*)(Bc + ((gt + jj * 128) << 4));
            GBAR();                              // all group raw reads done
#pragma unroll
            for (int jj = 0; jj < 8; jj++) {
                const int j = gt + jj * 128;
                const int r = j >> 5, c4 = j & 31;
                const float4 v = xa[jj];
                const u32 byte = ((r * 16 + ((c4 >> 1) ^ (r & 7))) << 4)
                               + ((c4 & 1) << 3);
                *(u64*)(Bc + byte) =
                    (u64)pack_f16x2(v.x, v.y) | ((u64)pack_f16x2(v.z, v.w) << 32);
            }
            // prefetch own edge raw (8KB) into E+spare — overlaps GEMM1-A
            const int nchk = 512;  // 32 rows x 16 chunks
#pragma unroll
            for (int jj = 0; jj < nchk / 128; jj++) {
                const int j = gt + jj * 128;
                const int r = j >> 4, c4 = j & 15;
                if (r0g + r < E)
                    cp16(bufE + (j << 4), edg + (size_t)(r0g + r) * EDGED + c4 * 4);
                else
                    *(float4*)(Bc + 8192 + (j << 4)) = make_float4(0.f, 0.f, 0.f, 0.f);
            }
            CP_COMMIT();
        }
        GBAR();                                  // X fp16 complete for group

        // ---- GEMM1 part A: src x W1[k<128] ----
        float acc[2][4][4];
#pragma unroll
        for (int mt = 0; mt < 2; mt++)
#pragma unroll
            for (int nt = 0; nt < 4; nt++)
#pragma unroll
                for (int q = 0; q < 4; q++) acc[mt][nt][q] = 0.f;
#pragma unroll 2
        for (int ks = 0; ks < 8; ks++)
            k_step<16, 16>(bufX, sb + OFF_W1AH, sb + OFF_W1AL,
                           wn, ks * 16, acc, lane);

        // ---- edge raw -> E fp16 (reg park, barrier, store) ----
        CP_WAIT0();
        {
            float4 ea[4];
#pragma unroll
            for (int jj = 0; jj < 4; jj++)
                ea[jj] = *(const float4*)(Bc + 8192 + ((gt + jj * 128) << 4));
            GBAR();                              // group edge raw reads done
#pragma unroll
            for (int jj = 0; jj < 4; jj++) {
                const int j = gt + jj * 128;
                const int r = j >> 4, c4 = j & 15;
                const float4 v = ea[jj];
                const u32 byte = ((r * 8 + ((c4 >> 1) ^ (r & 7))) << 4)
                               + ((c4 & 1) << 3);
                *(u64*)(Bc + 8192 + byte) =
                    (u64)pack_f16x2(v.x, v.y) | ((u64)pack_f16x2(v.z, v.w) << 32);
            }
        }
        GBAR();                                  // E fp16 complete

        // ---- GEMM1 part B: edge x W1[k>=128] ----
#pragma unroll 2
        for (int ks = 0; ks < 4; ks++)
            k_step<8, 8>(bufE, sb + OFF_W1BH, sb + OFF_W1BL,
                         wn, ks * 16, acc, lane);

        // ---- bias + LN partial sums (partials in own spare region) ----
        float s1[4] = {0.f, 0.f, 0.f, 0.f}, s2[4] = {0.f, 0.f, 0.f, 0.f};
#pragma unroll
        for (int mt = 0; mt < 2; mt++)
#pragma unroll
            for (int nt = 0; nt < 4; nt++) {
                const int c0 = wn * 32 + nt * 8 + 2 * tig;
                float* C = acc[mt][nt];
                C[0] += b1f[c0]; C[1] += b1f[c0 + 1];
                C[2] += b1f[c0]; C[3] += b1f[c0 + 1];
                s1[2 * mt]     += C[0] + C[1];
                s2[2 * mt]     += C[0] * C[0] + C[1] * C[1];
                s1[2 * mt + 1] += C[2] + C[3];
                s2[2 * mt + 1] += C[2] * C[2] + C[3] * C[3];
            }
#pragma unroll
        for (int j = 0; j < 4; j++) {
            s1[j] += __shfl_xor_sync(0xffffffffu, s1[j], 1);
            s1[j] += __shfl_xor_sync(0xffffffffu, s1[j], 2);
            s2[j] += __shfl_xor_sync(0xffffffffu, s2[j], 1);
            s2[j] += __shfl_xor_sync(0xffffffffu, s2[j], 2);
        }
        float2* part = (float2*)(Bc + 12288);    // 32 rows x 4 = 1KB in spare
        if (tig == 0) {
#pragma unroll
            for (int j = 0; j < 4; j++) {
                const int rl = ((j >> 1) << 4) + ((j & 1) << 3) + g;  // local row
                part[rl * 4 + wn] = make_float2(s1[j], s2[j]);
            }
        }
        GBAR();

        float mus[4], rss[4];
#pragma unroll
        for (int j = 0; j < 4; j++) {
            const int rl = ((j >> 1) << 4) + ((j & 1) << 3) + g;
            const float2 q0 = part[rl * 4 + 0], q1 = part[rl * 4 + 1];
            const float2 q2 = part[rl * 4 + 2], q3 = part[rl * 4 + 3];
            const float m1 = (q0.x + q1.x + q2.x + q3.x) * (1.0f / 128.0f);
            const float m2 = (q0.y + q1.y + q2.y + q3.y) * (1.0f / 128.0f);
            mus[j] = m1;
            rss[j] = rsqrtf(m2 - m1 * m1 + 1e-5f);
        }
        GBAR();                                  // partials consumed

        // ---- LN apply + SiLU -> H fp16 (own X region, swizzled) ----
#pragma unroll
        for (int mt = 0; mt < 2; mt++)
#pragma unroll
            for (int nt = 0; nt < 4; nt++) {
                const int c0 = wn * 32 + nt * 8 + 2 * tig;
                float* C = acc[mt][nt];
#pragma unroll
                for (int h = 0; h < 2; h++) {
                    const int j = 2 * mt + h;
                    const int rl = mt * 16 + h * 8 + g;
                    const float y0 = silu_f((C[2 * h + 0] - mus[j]) * rss[j] * gf[c0]     + btf[c0]);
                    const float y1 = silu_f((C[2 * h + 1] - mus[j]) * rss[j] * gf[c0 + 1] + btf[c0 + 1]);
                    const u32 byte = ((rl * 16 + ((c0 >> 3) ^ (rl & 7))) << 4)
                                   + ((c0 & 7) << 1);
                    *(u32*)(Bc + byte) = pack_f16x2(y0, y1);
                }
            }
        GBAR();                                  // full H rows visible in group

        // ---- GEMM2: H x W2 ----
#pragma unroll
        for (int mt = 0; mt < 2; mt++)
#pragma unroll
            for (int nt = 0; nt < 4; nt++)
#pragma unroll
                for (int q = 0; q < 4; q++) acc[mt][nt][q] = 0.f;
#pragma unroll 2
        for (int ks = 0; ks < 8; ks++)
            k_step<16, 16>(bufX, sb + OFF_W2H, sb + OFF_W2L,
                           wn, ks * 16, acc, lane);
        GBAR();                                  // group done reading H

        // ---- prefetch next tile's raw src into own slice (overlaps epi) ----
        if (ntile < ntiles) pf_src(ntile * BR);
        else CP_COMMIT();

        // ---- epilogue: bias + SiLU + store ----
#pragma unroll
        for (int mt = 0; mt < 2; mt++)
#pragma unroll
            for (int nt = 0; nt < 4; nt++) {
                const int c0 = wn * 32 + nt * 8 + 2 * tig;
                float* C = acc[mt][nt];
#pragma unroll
                for (int h = 0; h < 2; h++) {
                    const int row = r0g + mt * 16 + h * 8 + g;
                    if (row < E) {
                        float2 o;
                        o.x = silu_f(C[2 * h + 0] + b2f[c0]);
                        o.y = silu_f(C[2 * h + 1] + b2f[c0 + 1]);
                        *(float2*)(out + (size_t)row * OUTD + c0) = o;
                    }
                }
            }
    }
#undef GBAR
}

extern "C" void kernel_launch(void* const* d_in, const int* in_sizes, int n_in,
                              void* d_out, int out_size) {
    const float* src = (const float*)d_in[0];
    const float* edg = (const float*)d_in[1];
    const float* W1  = (const float*)d_in[2];
    const float* b1  = (const float*)d_in[3];
    const float* gam = (const float*)d_in[4];
    const float* bet = (const float*)d_in[5];
    const float* W2  = (const float*)d_in[6];
    const float* b2  = (const float*)d_in[7];
    float* out = (float*)d_out;

    const int E = in_sizes[0] / NODE;
    const int ntiles = (E + BR - 1) / BR;

    cudaFuncSetAttribute(edge_mlp_mma,
                         cudaFuncAttributeMaxDynamicSharedMemorySize, SMEM_BYTES);

    int nsm = 148;
    if (cudaDeviceGetAttribute(&nsm, cudaDevAttrMultiProcessorCount, 0) != cudaSuccess
        || nsm <= 0)
        nsm = 148;
    const int grid = nsm < ntiles ? nsm : ntiles;

    edge_mlp_mma<<<grid, THREADS, SMEM_BYTES>>>(src, edg, W1, b1, gam, bet,
                                                W2, b2, out, E, ntiles);
}